// round 9
// baseline (speedup 1.0000x reference)
#include <cuda_runtime.h>

// SelfNorm collapsed: out = x*std_w + mean*(mean_w - std_w), per (b,c) row.
// PERSISTENT kernel, 256 thr/CTA, 5 CTAs/SM (grid 740, one resident wave).
// Half-row register prefetch: 2 of 4 float4 of the next row are loaded
// before the barrier (hides DRAM latency under reduce/MLP/store); the other
// half loads into dead registers after the stores. One barrier per row
// (ping-pong partials). Lane-parallel MLPs, weights hoisted out of the loop.

#define HW 3136          // 56*56
#define F4 784           // HW/4 = 3*256 + 16
#define NTHREADS 256
#define NROWS 8192       // B*C
#define CTAS_PER_SM 5
#define GRID (148 * CTAS_PER_SM)   // 740
#define EPS 1e-5f

__device__ __forceinline__ void acc4(const float4& a, float& s, float& sq) {
    s += a.x + a.y + a.z + a.w;
    sq = fmaf(a.x, a.x, sq); sq = fmaf(a.y, a.y, sq);
    sq = fmaf(a.z, a.z, sq); sq = fmaf(a.w, a.w, sq);
}

__device__ __forceinline__ float4 xform(const float4& a, float al, float be) {
    float4 r;
    r.x = fmaf(a.x, al, be);
    r.y = fmaf(a.y, al, be);
    r.z = fmaf(a.z, al, be);
    r.w = fmaf(a.w, al, be);
    return r;
}

__global__ void __launch_bounds__(NTHREADS, CTAS_PER_SM)
selfnorm_kernel(const float4* __restrict__ x,
                const float* __restrict__ W1m, const float* __restrict__ b1m,
                const float* __restrict__ W2m, const float* __restrict__ b2m,
                const float* __restrict__ W1s, const float* __restrict__ b1s,
                const float* __restrict__ W2s, const float* __restrict__ b2s,
                float4* __restrict__ out) {
    __shared__ float ps[2][8], psq[2][8];

    const int t    = threadIdx.x;
    const int lane = t & 31;
    const int wid  = t >> 5;
    const bool rem = (t < 16);          // 784 - 3*256

    // ---- Hoisted MLP weights (lane<16: mean-MLP unit, lane>=16: std-MLP) ----
    const int  j = lane & 15;
    const bool is_m = (lane < 16);
    const float w1a = __ldg((is_m ? W1m : W1s) + 2 * j);
    const float w1b = __ldg((is_m ? W1m : W1s) + 2 * j + 1);
    const float bb1 = __ldg((is_m ? b1m : b1s) + j);
    const float w2  = __ldg((is_m ? W2m : W2s) + j);
    const float bb2 = __ldg( is_m ? b2m : b2s);

    // ---- Prologue: load first row ----
    int row = blockIdx.x;
    {
        const float4* xr = x + (size_t)row * F4;
        // loads issued below via a0..a3 initialization
    }
    const float4* xr0 = x + (size_t)row * F4;
    float4 a0 = __ldcs(xr0 + t);
    float4 a1 = __ldcs(xr0 + t + 256);
    float4 a2 = __ldcs(xr0 + t + 512);
    float4 a3 = rem ? __ldcs(xr0 + 768 + t) : make_float4(0.f, 0.f, 0.f, 0.f);

    int pb = 0;
    for (; row < NROWS; row += GRID, pb ^= 1) {
        const int nrow = row + GRID;
        const bool has_next = (nrow < NROWS);
        const float4* xn = x + (size_t)nrow * F4;

        // ---- Stats from current registers ----
        float s = 0.0f, sq = 0.0f;
        acc4(a0, s, sq); acc4(a1, s, sq); acc4(a2, s, sq);
        if (rem) acc4(a3, s, sq);

        // ---- Prefetch HALF of next row (in flight across barrier/MLP) ----
        float4 b0, b1;
        if (has_next) {
            b0 = __ldcs(xn + t);
            b1 = __ldcs(xn + t + 256);
        }

        // ---- Warp reduce, single barrier (ping-pong partials) ----
        #pragma unroll
        for (int o = 16; o > 0; o >>= 1) {
            s  += __shfl_xor_sync(0xffffffffu, s,  o);
            sq += __shfl_xor_sync(0xffffffffu, sq, o);
        }
        if (lane == 0) { ps[pb][wid] = s; psq[pb][wid] = sq; }
        __syncthreads();

        float ts = 0.0f, tsq = 0.0f;
        #pragma unroll
        for (int i = 0; i < 8; i++) { ts += ps[pb][i]; tsq += psq[pb][i]; }

        const float n = (float)HW;
        const float mean = ts / n;
        float var = (tsq - n * mean * mean) / (n - 1.0f);
        var = fmaxf(var, 0.0f);
        const float std = sqrtf(var + EPS);

        // ---- Lane-parallel MLPs ----
        float h = fmaf(w1a, mean, fmaf(w1b, std, bb1));
        h = fmaxf(h, 0.0f);
        float p = w2 * h;
        #pragma unroll
        for (int o = 8; o > 0; o >>= 1)
            p += __shfl_xor_sync(0xffffffffu, p, o);
        float z = p + bb2;
        float sig = 1.0f / (1.0f + __expf(-z));

        const float mean_w = __shfl_sync(0xffffffffu, sig, 0);
        const float std_w  = __shfl_sync(0xffffffffu, sig, 16);
        const float alpha = std_w;
        const float beta  = mean * (mean_w - std_w);

        // ---- Transform + streaming store ----
        float4* orow = out + (size_t)row * F4;
        __stcs(orow + t,       xform(a0, alpha, beta));
        __stcs(orow + t + 256, xform(a1, alpha, beta));
        __stcs(orow + t + 512, xform(a2, alpha, beta));
        if (rem) __stcs(orow + 768 + t, xform(a3, alpha, beta));

        // ---- Load remaining half of next row into dead regs, rotate ----
        if (has_next) {
            a2 = __ldcs(xn + t + 512);
            if (rem) a3 = __ldcs(xn + 768 + t);
            a0 = b0;
            a1 = b1;
        }
    }
}

extern "C" void kernel_launch(void* const* d_in, const int* in_sizes, int n_in,
                              void* d_out, int out_size) {
    const float4* x  = (const float4*)d_in[0];
    const float* W1m = (const float*)d_in[1];
    const float* b1m = (const float*)d_in[2];
    const float* W2m = (const float*)d_in[3];
    const float* b2m = (const float*)d_in[4];
    const float* W1s = (const float*)d_in[5];
    const float* b1s = (const float*)d_in[6];
    const float* W2s = (const float*)d_in[7];
    const float* b2s = (const float*)d_in[8];
    float4* out = (float4*)d_out;

    selfnorm_kernel<<<GRID, NTHREADS>>>(x, W1m, b1m, W2m, b2m,
                                        W1s, b1s, W2s, b2s, out);
}

// round 10
// speedup vs baseline: 1.0523x; 1.0523x over previous
#include <cuda_runtime.h>

// SelfNorm collapsed: out = x*std_w + mean*(mean_w - std_w), per (b,c) row.
// One CTA (256 thr) per row (grid 8192 — smallest wall overhead measured).
// Row in registers, x read from DRAM once (streaming). Single barrier.
// Remainder (16 float4) balanced across all 8 warps (2 each, lanes 0-1)
// so no straggler warp delays the barrier. Lane-parallel MLPs.

#define HW 3136          // 56*56
#define F4 784           // HW/4 = 3*256 + 16
#define NTHREADS 256
#define EPS 1e-5f

__device__ __forceinline__ void acc4(const float4& a, float& s, float& sq) {
    s += a.x + a.y + a.z + a.w;
    sq = fmaf(a.x, a.x, sq); sq = fmaf(a.y, a.y, sq);
    sq = fmaf(a.z, a.z, sq); sq = fmaf(a.w, a.w, sq);
}

__device__ __forceinline__ float4 xform(const float4& a, float al, float be) {
    float4 r;
    r.x = fmaf(a.x, al, be);
    r.y = fmaf(a.y, al, be);
    r.z = fmaf(a.z, al, be);
    r.w = fmaf(a.w, al, be);
    return r;
}

__global__ void __launch_bounds__(NTHREADS)
selfnorm_kernel(const float4* __restrict__ x,
                const float* __restrict__ W1m, const float* __restrict__ b1m,
                const float* __restrict__ W2m, const float* __restrict__ b2m,
                const float* __restrict__ W1s, const float* __restrict__ b1s,
                const float* __restrict__ W2s, const float* __restrict__ b2s,
                float4* __restrict__ out) {
    __shared__ float ps[8], psq[8];

    const int t    = threadIdx.x;
    const int lane = t & 31;
    const int wid  = t >> 5;
    // Balanced remainder: warp w takes extras 768+2w (lane 0) and 768+2w+1 (lane 1)
    const bool rem = (lane < 2);
    const int  ridx = 768 + 2 * wid + lane;

    const float4* __restrict__ xr   = x   + (size_t)blockIdx.x * F4;
    float4*       __restrict__ orow = out + (size_t)blockIdx.x * F4;

    // ---- Load whole row into registers (streaming), accumulate stats ----
    float4 a0 = __ldcs(xr + t);
    float4 a1 = __ldcs(xr + t + 256);
    float4 a2 = __ldcs(xr + t + 512);
    float4 a3;
    if (rem) a3 = __ldcs(xr + ridx);

    float s = 0.0f, sq = 0.0f;
    acc4(a0, s, sq);
    acc4(a1, s, sq);
    acc4(a2, s, sq);
    if (rem) acc4(a3, s, sq);

    // ---- Warp reduce, one barrier ----
    #pragma unroll
    for (int o = 16; o > 0; o >>= 1) {
        s  += __shfl_xor_sync(0xffffffffu, s,  o);
        sq += __shfl_xor_sync(0xffffffffu, sq, o);
    }
    if (lane == 0) { ps[wid] = s; psq[wid] = sq; }
    __syncthreads();

    // ---- Every thread: total sums -> mean/std ----
    float ts = 0.0f, tsq = 0.0f;
    #pragma unroll
    for (int i = 0; i < 8; i++) { ts += ps[i]; tsq += psq[i]; }

    const float n = (float)HW;
    const float mean = ts / n;
    float var = (tsq - n * mean * mean) / (n - 1.0f);
    var = fmaxf(var, 0.0f);
    const float std = sqrtf(var + EPS);

    // ---- Lane-parallel MLPs within each warp ----
    const int  j = lane & 15;
    const bool is_m = (lane < 16);
    const float* __restrict__ W1 = is_m ? W1m : W1s;
    const float* __restrict__ B1 = is_m ? b1m : b1s;
    const float* __restrict__ W2 = is_m ? W2m : W2s;
    const float* __restrict__ B2 = is_m ? b2m : b2s;

    float h = fmaf(__ldg(W1 + 2 * j), mean,
              fmaf(__ldg(W1 + 2 * j + 1), std, __ldg(B1 + j)));
    h = fmaxf(h, 0.0f);
    float p = __ldg(W2 + j) * h;
    #pragma unroll
    for (int o = 8; o > 0; o >>= 1)
        p += __shfl_xor_sync(0xffffffffu, p, o);
    float z = p + __ldg(B2);
    float sig = 1.0f / (1.0f + __expf(-z));

    const float mean_w = __shfl_sync(0xffffffffu, sig, 0);
    const float std_w  = __shfl_sync(0xffffffffu, sig, 16);
    const float alpha = std_w;
    const float beta  = mean * (mean_w - std_w);

    // ---- Transform registers, streaming store ----
    __stcs(orow + t,       xform(a0, alpha, beta));
    __stcs(orow + t + 256, xform(a1, alpha, beta));
    __stcs(orow + t + 512, xform(a2, alpha, beta));
    if (rem) __stcs(orow + ridx, xform(a3, alpha, beta));
}

extern "C" void kernel_launch(void* const* d_in, const int* in_sizes, int n_in,
                              void* d_out, int out_size) {
    const float4* x  = (const float4*)d_in[0];
    const float* W1m = (const float*)d_in[1];
    const float* b1m = (const float*)d_in[2];
    const float* W2m = (const float*)d_in[3];
    const float* b2m = (const float*)d_in[4];
    const float* W1s = (const float*)d_in[5];
    const float* b1s = (const float*)d_in[6];
    const float* W2s = (const float*)d_in[7];
    const float* b2s = (const float*)d_in[8];
    float4* out = (float4*)d_out;

    const int rows = 32 * 256;  // B * C = 8192 CTAs, one row each
    selfnorm_kernel<<<rows, NTHREADS>>>(x, W1m, b1m, W2m, b2m,
                                        W1s, b1s, W2s, b2s, out);
}

// round 11
// speedup vs baseline: 1.0599x; 1.0073x over previous
#include <cuda_runtime.h>

// SelfNorm collapsed: out = x*std_w + mean*(mean_w - std_w), per (b,c) row.
// One CTA (256 thr) per row, grid 8192. Row's main 768 float4 in registers
// (12 regs/thread); the 16-remainder is bounced through a 256B smem buffer
// so nothing extra is live across the barrier. Register budget forced to 32
// via __launch_bounds__(256, 8) -> 8 CTAs/SM (100% occupancy) to maximize
// in-flight DRAM demand. Single barrier; lane-parallel MLPs.

#define HW 3136          // 56*56
#define F4 784           // HW/4 = 3*256 + 16
#define NTHREADS 256
#define EPS 1e-5f

__device__ __forceinline__ void acc4(const float4& a, float& s, float& sq) {
    s += a.x + a.y + a.z + a.w;
    sq = fmaf(a.x, a.x, sq); sq = fmaf(a.y, a.y, sq);
    sq = fmaf(a.z, a.z, sq); sq = fmaf(a.w, a.w, sq);
}

__device__ __forceinline__ float4 xform(const float4& a, float al, float be) {
    float4 r;
    r.x = fmaf(a.x, al, be);
    r.y = fmaf(a.y, al, be);
    r.z = fmaf(a.z, al, be);
    r.w = fmaf(a.w, al, be);
    return r;
}

__global__ void __launch_bounds__(NTHREADS, 8)
selfnorm_kernel(const float4* __restrict__ x,
                const float* __restrict__ W1m, const float* __restrict__ b1m,
                const float* __restrict__ W2m, const float* __restrict__ b2m,
                const float* __restrict__ W1s, const float* __restrict__ b1s,
                const float* __restrict__ W2s, const float* __restrict__ b2s,
                float4* __restrict__ out) {
    __shared__ float ps[8], psq[8];
    __shared__ float4 tailbuf[16];

    const int t    = threadIdx.x;
    const int lane = t & 31;
    const int wid  = t >> 5;
    const bool rem = (t < 16);

    const float4* __restrict__ xr   = x   + (size_t)blockIdx.x * F4;
    float4*       __restrict__ orow = out + (size_t)blockIdx.x * F4;

    // ---- Load row (streaming): 3 float4 in regs, tail bounced via smem ----
    float4 a0 = __ldcs(xr + t);
    float4 a1 = __ldcs(xr + t + 256);
    float4 a2 = __ldcs(xr + t + 512);

    float s = 0.0f, sq = 0.0f;
    if (rem) {
        float4 a3 = __ldcs(xr + 768 + t);
        acc4(a3, s, sq);
        tailbuf[t] = a3;          // parked; a3 dead before the barrier
    }
    acc4(a0, s, sq);
    acc4(a1, s, sq);
    acc4(a2, s, sq);

    // ---- Warp reduce, one barrier (also publishes tailbuf) ----
    #pragma unroll
    for (int o = 16; o > 0; o >>= 1) {
        s  += __shfl_xor_sync(0xffffffffu, s,  o);
        sq += __shfl_xor_sync(0xffffffffu, sq, o);
    }
    if (lane == 0) { ps[wid] = s; psq[wid] = sq; }
    __syncthreads();

    // ---- Every thread: total sums -> mean/std ----
    float ts = 0.0f, tsq = 0.0f;
    #pragma unroll
    for (int i = 0; i < 8; i++) { ts += ps[i]; tsq += psq[i]; }

    const float n = (float)HW;
    const float mean = ts / n;
    float var = (tsq - n * mean * mean) / (n - 1.0f);
    var = fmaxf(var, 0.0f);
    const float std = sqrtf(var + EPS);

    // ---- Lane-parallel MLPs within each warp ----
    const int  j = lane & 15;
    const bool is_m = (lane < 16);
    const float* __restrict__ W1 = is_m ? W1m : W1s;
    const float* __restrict__ B1 = is_m ? b1m : b1s;
    const float* __restrict__ W2 = is_m ? W2m : W2s;
    const float* __restrict__ B2 = is_m ? b2m : b2s;

    float h = fmaf(__ldg(W1 + 2 * j), mean,
              fmaf(__ldg(W1 + 2 * j + 1), std, __ldg(B1 + j)));
    h = fmaxf(h, 0.0f);
    float p = __ldg(W2 + j) * h;
    #pragma unroll
    for (int o = 8; o > 0; o >>= 1)
        p += __shfl_xor_sync(0xffffffffu, p, o);
    float z = p + __ldg(B2);
    float sig = 1.0f / (1.0f + __expf(-z));

    const float mean_w = __shfl_sync(0xffffffffu, sig, 0);
    const float std_w  = __shfl_sync(0xffffffffu, sig, 16);
    const float alpha = std_w;
    const float beta  = mean * (mean_w - std_w);

    // ---- Transform + streaming store (tail from smem) ----
    __stcs(orow + t,       xform(a0, alpha, beta));
    __stcs(orow + t + 256, xform(a1, alpha, beta));
    __stcs(orow + t + 512, xform(a2, alpha, beta));
    if (rem)
        __stcs(orow + 768 + t, xform(tailbuf[t], alpha, beta));
}

extern "C" void kernel_launch(void* const* d_in, const int* in_sizes, int n_in,
                              void* d_out, int out_size) {
    const float4* x  = (const float4*)d_in[0];
    const float* W1m = (const float*)d_in[1];
    const float* b1m = (const float*)d_in[2];
    const float* W2m = (const float*)d_in[3];
    const float* b2m = (const float*)d_in[4];
    const float* W1s = (const float*)d_in[5];
    const float* b1s = (const float*)d_in[6];
    const float* W2s = (const float*)d_in[7];
    const float* b2s = (const float*)d_in[8];
    float4* out = (float4*)d_out;

    const int rows = 32 * 256;  // B * C = 8192 CTAs, one row each
    selfnorm_kernel<<<rows, NTHREADS>>>(x, W1m, b1m, W2m, b2m,
                                        W1s, b1s, W2s, b2s, out);
}